// round 10
// baseline (speedup 1.0000x reference)

#include <cuda_runtime.h>

#define BATCH 4
#define SEQ   2048
#define CH    768
#define HEADS 12
#define HDIM  64

// Scratch (allocation-free rule: __device__ globals)
__device__ __align__(16) float g_q[(size_t)BATCH * HEADS * SEQ * HDIM];
__device__ __align__(16) float g_k[(size_t)BATCH * HEADS * SEQ * HDIM];
__device__ __align__(16) float g_v[(size_t)BATCH * HEADS * SEQ * HDIM];
__device__ __align__(16) float g_att[(size_t)BATCH * SEQ * CH];

// ---------------------------------------------------------------------------
// Kernel 1: QKV projection. out = X @ W^T + b, scattered to Q/K/V [B,H,N,D].
// 128x128x16 block tile, 256 threads, 8x8 per-thread microtile.
// Smem stored k-major ([k][m]) so microtile loads are contiguous float4.
// ---------------------------------------------------------------------------
__global__ __launch_bounds__(256) void qkv_gemm_kernel(
    const float* __restrict__ X, const float* __restrict__ W,
    const float* __restrict__ bias)
{
    __shared__ float As[16][132];
    __shared__ float Bs[16][132];
    const int bm = blockIdx.y << 7;
    const int bn = blockIdx.x << 7;
    const int tid = threadIdx.x;
    const int ty = tid >> 4;
    const int tx = tid & 15;

    float acc[8][8];
#pragma unroll
    for (int i = 0; i < 8; i++)
#pragma unroll
        for (int j = 0; j < 8; j++) acc[i][j] = 0.f;

    const int lr = tid >> 2;
    const int lc = (tid & 3) << 2;

    for (int k0 = 0; k0 < CH; k0 += 16) {
#pragma unroll
        for (int rep = 0; rep < 2; rep++) {
            const int r = lr + rep * 64;
            float4 av = *(const float4*)(X + (size_t)(bm + r) * CH + k0 + lc);
            As[lc + 0][r] = av.x; As[lc + 1][r] = av.y;
            As[lc + 2][r] = av.z; As[lc + 3][r] = av.w;
            float4 bv = *(const float4*)(W + (size_t)(bn + r) * CH + k0 + lc);
            Bs[lc + 0][r] = bv.x; Bs[lc + 1][r] = bv.y;
            Bs[lc + 2][r] = bv.z; Bs[lc + 3][r] = bv.w;
        }
        __syncthreads();
#pragma unroll
        for (int k = 0; k < 16; k++) {
            float a[8], bb[8];
            *(float4*)(a)      = *(const float4*)&As[k][ty * 8];
            *(float4*)(a + 4)  = *(const float4*)&As[k][ty * 8 + 4];
            *(float4*)(bb)     = *(const float4*)&Bs[k][tx * 8];
            *(float4*)(bb + 4) = *(const float4*)&Bs[k][tx * 8 + 4];
#pragma unroll
            for (int i = 0; i < 8; i++)
#pragma unroll
                for (int j = 0; j < 8; j++)
                    acc[i][j] = fmaf(a[i], bb[j], acc[i][j]);
        }
        __syncthreads();
    }

#pragma unroll
    for (int i = 0; i < 8; i++) {
        const int gm = bm + ty * 8 + i;
        const int bi = gm >> 11;          // / SEQ
        const int ni = gm & (SEQ - 1);
#pragma unroll
        for (int jj = 0; jj < 2; jj++) {
            const int gn = bn + tx * 8 + jj * 4;
            const int which = gn / CH;          // 0=Q, 1=K, 2=V (128-tile never straddles)
            const int rem = gn - which * CH;
            const int hh = rem >> 6;
            const int dd = rem & 63;
            float* dst = (which == 0) ? g_q : ((which == 1) ? g_k : g_v);
            float4 v;
            v.x = acc[i][jj * 4 + 0] + bias[gn + 0];
            v.y = acc[i][jj * 4 + 1] + bias[gn + 1];
            v.z = acc[i][jj * 4 + 2] + bias[gn + 2];
            v.w = acc[i][jj * 4 + 3] + bias[gn + 3];
            *(float4*)(dst + ((((size_t)bi * HEADS + hh) * SEQ + ni) << 6) + dd) = v;
        }
    }
}

// ---------------------------------------------------------------------------
// Kernel 2: flash attention, fp32, online softmax.
// Block: one (b,h), 128 query rows. Loop over 32 KV tiles of 64 keys.
// 256 threads as 16(ty) x 16(tx); per-thread 8 rows x 4 cols.
// Output written directly in [B, N, H*D] = [B,N,C] layout.
// ---------------------------------------------------------------------------
#define ATTN_SMEM_FLOATS (64 * 132 + 64 * 68 + 64 * 68 + 64 * 132)
#define ATTN_SMEM_BYTES  (ATTN_SMEM_FLOATS * 4)

__global__ __launch_bounds__(256) void attn_kernel()
{
    extern __shared__ float sm[];
    float* Qs = sm;                       // [d][row]  64 x 132 (128 rows + pad)
    float* Ks = Qs + 64 * 132;            // [d][key]  64 x 68
    float* Vs = Ks + 64 * 68;             // [key][d]  64 x 68
    float* Ps = Vs + 64 * 68;             // [key][row] 64 x 132

    const int n0 = blockIdx.x << 7;       // query tile start
    const int h  = blockIdx.y;
    const int b  = blockIdx.z;
    const int tid = threadIdx.x;
    const int ty = tid >> 4;
    const int tx = tid & 15;

    const float* qbase = g_q + (((size_t)b * HEADS + h) * SEQ + n0) * HDIM;
    const float* kbase = g_k + ((size_t)b * HEADS + h) * SEQ * HDIM;
    const float* vbase = g_v + ((size_t)b * HEADS + h) * SEQ * HDIM;

    // Load Q tile [128][64], store transposed [d][row]
#pragma unroll
    for (int it = 0; it < 8; it++) {
        const int lin = (it * 256 + tid) << 2;
        const int row = lin >> 6;
        const int d   = lin & 63;
        float4 v = *(const float4*)(qbase + lin);
        Qs[(d + 0) * 132 + row] = v.x;
        Qs[(d + 1) * 132 + row] = v.y;
        Qs[(d + 2) * 132 + row] = v.z;
        Qs[(d + 3) * 132 + row] = v.w;
    }

    float o[8][4];
    float mrow[8], lrow[8];
#pragma unroll
    for (int i = 0; i < 8; i++) {
        mrow[i] = -1e30f;
        lrow[i] = 0.f;
#pragma unroll
        for (int j = 0; j < 4; j++) o[i][j] = 0.f;
    }

    for (int kt = 0; kt < SEQ / 64; kt++) {
        const float* kb = kbase + (size_t)kt * 64 * HDIM;
        const float* vb = vbase + (size_t)kt * 64 * HDIM;
        __syncthreads();   // prior-iteration readers of Ks/Vs done (also covers Qs fill)
#pragma unroll
        for (int it = 0; it < 4; it++) {
            const int lin = (it * 256 + tid) << 2;
            const int row = lin >> 6;
            const int d   = lin & 63;
            float4 kv = *(const float4*)(kb + lin);
            Ks[(d + 0) * 68 + row] = kv.x;
            Ks[(d + 1) * 68 + row] = kv.y;
            Ks[(d + 2) * 68 + row] = kv.z;
            Ks[(d + 3) * 68 + row] = kv.w;
            float4 vv = *(const float4*)(vb + lin);
            *(float4*)&Vs[row * 68 + d] = vv;
        }
        __syncthreads();

        // S = Q @ K^T  (per-thread 8x4)
        float s[8][4];
#pragma unroll
        for (int i = 0; i < 8; i++)
#pragma unroll
            for (int j = 0; j < 4; j++) s[i][j] = 0.f;

#pragma unroll 8
        for (int d = 0; d < 64; d++) {
            float a[8];
            *(float4*)(a)     = *(const float4*)&Qs[d * 132 + ty * 8];
            *(float4*)(a + 4) = *(const float4*)&Qs[d * 132 + ty * 8 + 4];
            float4 kk = *(const float4*)&Ks[d * 68 + tx * 4];
#pragma unroll
            for (int i = 0; i < 8; i++) {
                s[i][0] = fmaf(a[i], kk.x, s[i][0]);
                s[i][1] = fmaf(a[i], kk.y, s[i][1]);
                s[i][2] = fmaf(a[i], kk.z, s[i][2]);
                s[i][3] = fmaf(a[i], kk.w, s[i][3]);
            }
        }

        // Online softmax update (row groups = 16 lanes sharing ty)
#pragma unroll
        for (int i = 0; i < 8; i++) {
            const float scale = 0.125f;  // 64^-0.5
            s[i][0] *= scale; s[i][1] *= scale; s[i][2] *= scale; s[i][3] *= scale;
            float mx = fmaxf(fmaxf(s[i][0], s[i][1]), fmaxf(s[i][2], s[i][3]));
#pragma unroll
            for (int off = 1; off < 16; off <<= 1)
                mx = fmaxf(mx, __shfl_xor_sync(0xffffffffu, mx, off, 16));
            const float mnew = fmaxf(mrow[i], mx);
            const float alpha = __expf(mrow[i] - mnew);
            mrow[i] = mnew;
            float rs = 0.f;
#pragma unroll
            for (int j = 0; j < 4; j++) {
                const float p = __expf(s[i][j] - mnew);
                s[i][j] = p;
                rs += p;
            }
#pragma unroll
            for (int off = 1; off < 16; off <<= 1)
                rs += __shfl_xor_sync(0xffffffffu, rs, off, 16);
            lrow[i] = lrow[i] * alpha + rs;
#pragma unroll
            for (int j = 0; j < 4; j++) o[i][j] *= alpha;
            // stage P transposed: [key][row]
#pragma unroll
            for (int j = 0; j < 4; j++)
                Ps[(tx * 4 + j) * 132 + ty * 8 + i] = s[i][j];
        }
        __syncthreads();

        // O += P @ V  (per-thread rows ty*8.., dims tx*4..)
#pragma unroll 8
        for (int j = 0; j < 64; j++) {
            float p[8];
            *(float4*)(p)     = *(const float4*)&Ps[j * 132 + ty * 8];
            *(float4*)(p + 4) = *(const float4*)&Ps[j * 132 + ty * 8 + 4];
            float4 vv = *(const float4*)&Vs[j * 68 + tx * 4];
#pragma unroll
            for (int i = 0; i < 8; i++) {
                o[i][0] = fmaf(p[i], vv.x, o[i][0]);
                o[i][1] = fmaf(p[i], vv.y, o[i][1]);
                o[i][2] = fmaf(p[i], vv.z, o[i][2]);
                o[i][3] = fmaf(p[i], vv.w, o[i][3]);
            }
        }
    }

    // Normalize and write [B,N,C]
    float* ob = g_att + ((size_t)b * SEQ + n0) * CH + h * HDIM;
#pragma unroll
    for (int i = 0; i < 8; i++) {
        const float inv = 1.0f / lrow[i];
        float4 v;
        v.x = o[i][0] * inv; v.y = o[i][1] * inv;
        v.z = o[i][2] * inv; v.w = o[i][3] * inv;
        *(float4*)(ob + (size_t)(ty * 8 + i) * CH + tx * 4) = v;
    }
}

// ---------------------------------------------------------------------------
// Kernel 3: output projection. out = g_att @ proj_w^T + proj_b.
// ---------------------------------------------------------------------------
__global__ __launch_bounds__(256) void proj_gemm_kernel(
    const float* __restrict__ W, const float* __restrict__ bias,
    float* __restrict__ out)
{
    __shared__ float As[16][132];
    __shared__ float Bs[16][132];
    const int bm = blockIdx.y << 7;
    const int bn = blockIdx.x << 7;
    const int tid = threadIdx.x;
    const int ty = tid >> 4;
    const int tx = tid & 15;

    float acc[8][8];
#pragma unroll
    for (int i = 0; i < 8; i++)
#pragma unroll
        for (int j = 0; j < 8; j++) acc[i][j] = 0.f;

    const int lr = tid >> 2;
    const int lc = (tid & 3) << 2;

    for (int k0 = 0; k0 < CH; k0 += 16) {
#pragma unroll
        for (int rep = 0; rep < 2; rep++) {
            const int r = lr + rep * 64;
            float4 av = *(const float4*)(g_att + (size_t)(bm + r) * CH + k0 + lc);
            As[lc + 0][r] = av.x; As[lc + 1][r] = av.y;
            As[lc + 2][r] = av.z; As[lc + 3][r] = av.w;
            float4 bv = *(const float4*)(W + (size_t)(bn + r) * CH + k0 + lc);
            Bs[lc + 0][r] = bv.x; Bs[lc + 1][r] = bv.y;
            Bs[lc + 2][r] = bv.z; Bs[lc + 3][r] = bv.w;
        }
        __syncthreads();
#pragma unroll
        for (int k = 0; k < 16; k++) {
            float a[8], bb[8];
            *(float4*)(a)      = *(const float4*)&As[k][ty * 8];
            *(float4*)(a + 4)  = *(const float4*)&As[k][ty * 8 + 4];
            *(float4*)(bb)     = *(const float4*)&Bs[k][tx * 8];
            *(float4*)(bb + 4) = *(const float4*)&Bs[k][tx * 8 + 4];
#pragma unroll
            for (int i = 0; i < 8; i++)
#pragma unroll
                for (int j = 0; j < 8; j++)
                    acc[i][j] = fmaf(a[i], bb[j], acc[i][j]);
        }
        __syncthreads();
    }

#pragma unroll
    for (int i = 0; i < 8; i++) {
        const int gm = bm + ty * 8 + i;
#pragma unroll
        for (int jj = 0; jj < 2; jj++) {
            const int gn = bn + tx * 8 + jj * 4;
            float4 v;
            v.x = acc[i][jj * 4 + 0] + bias[gn + 0];
            v.y = acc[i][jj * 4 + 1] + bias[gn + 1];
            v.z = acc[i][jj * 4 + 2] + bias[gn + 2];
            v.w = acc[i][jj * 4 + 3] + bias[gn + 3];
            *(float4*)(out + (size_t)gm * CH + gn) = v;
        }
    }
}

// ---------------------------------------------------------------------------
extern "C" void kernel_launch(void* const* d_in, const int* in_sizes, int n_in,
                              void* d_out, int out_size)
{
    const float* x      = (const float*)d_in[0];
    const float* qkv_w  = (const float*)d_in[1];
    const float* qkv_b  = (const float*)d_in[2];
    const float* proj_w = (const float*)d_in[3];
    const float* proj_b = (const float*)d_in[4];
    float* out = (float*)d_out;

    (void)in_sizes; (void)n_in; (void)out_size;

    // QKV projection: M=8192, N=2304, K=768
    qkv_gemm_kernel<<<dim3(2304 / 128, (BATCH * SEQ) / 128), 256>>>(x, qkv_w, qkv_b);

    // Flash attention
    cudaFuncSetAttribute(attn_kernel, cudaFuncAttributeMaxDynamicSharedMemorySize,
                         ATTN_SMEM_BYTES);
    attn_kernel<<<dim3(SEQ / 128, HEADS, BATCH), 256, ATTN_SMEM_BYTES>>>();

    // Output projection: M=8192, N=768, K=768
    proj_gemm_kernel<<<dim3(CH / 128, (BATCH * SEQ) / 128), 256>>>(proj_b ? proj_w : proj_w, proj_b, out);
}

// round 11
// speedup vs baseline: 1.0244x; 1.0244x over previous
#include <cuda_runtime.h>

#define BATCH 4
#define SEQ   2048
#define CH    768
#define HEADS 12
#define HDIM  64

// Scratch (allocation-free rule: __device__ globals)
__device__ __align__(16) float g_q[(size_t)BATCH * HEADS * SEQ * HDIM];
__device__ __align__(16) float g_k[(size_t)BATCH * HEADS * SEQ * HDIM];
__device__ __align__(16) float g_v[(size_t)BATCH * HEADS * SEQ * HDIM];
__device__ __align__(16) float g_att[(size_t)BATCH * SEQ * CH];

// ---------------------------------------------------------------------------
// Kernel 1: QKV projection. out = X @ W^T + b, scattered to Q/K/V [B,H,N,D].
// 128x128x16 block tile, 256 threads, 8x8 per-thread microtile.
// Double-buffered smem (one barrier per k-tile) + register prefetch of the
// next k-tile's global loads. Smem k-major so microtile loads are float4.
// ---------------------------------------------------------------------------
__global__ __launch_bounds__(256, 2) void qkv_gemm_kernel(
    const float* __restrict__ X, const float* __restrict__ W,
    const float* __restrict__ bias)
{
    __shared__ float As[2][16][132];
    __shared__ float Bs[2][16][132];
    const int bm = blockIdx.y << 7;
    const int bn = blockIdx.x << 7;
    const int tid = threadIdx.x;
    const int ty = tid >> 4;
    const int tx = tid & 15;
    const int lr = tid >> 2;
    const int lc = (tid & 3) << 2;

    float acc[8][8];
#pragma unroll
    for (int i = 0; i < 8; i++)
#pragma unroll
        for (int j = 0; j < 8; j++) acc[i][j] = 0.f;

    // prologue: global-load k-tile 0 and stage into buffer 0
    float4 rA0 = *(const float4*)(X + (size_t)(bm + lr) * CH + lc);
    float4 rA1 = *(const float4*)(X + (size_t)(bm + lr + 64) * CH + lc);
    float4 rB0 = *(const float4*)(W + (size_t)(bn + lr) * CH + lc);
    float4 rB1 = *(const float4*)(W + (size_t)(bn + lr + 64) * CH + lc);
    As[0][lc + 0][lr] = rA0.x; As[0][lc + 1][lr] = rA0.y;
    As[0][lc + 2][lr] = rA0.z; As[0][lc + 3][lr] = rA0.w;
    As[0][lc + 0][lr + 64] = rA1.x; As[0][lc + 1][lr + 64] = rA1.y;
    As[0][lc + 2][lr + 64] = rA1.z; As[0][lc + 3][lr + 64] = rA1.w;
    Bs[0][lc + 0][lr] = rB0.x; Bs[0][lc + 1][lr] = rB0.y;
    Bs[0][lc + 2][lr] = rB0.z; Bs[0][lc + 3][lr] = rB0.w;
    Bs[0][lc + 0][lr + 64] = rB1.x; Bs[0][lc + 1][lr + 64] = rB1.y;
    Bs[0][lc + 2][lr + 64] = rB1.z; Bs[0][lc + 3][lr + 64] = rB1.w;
    __syncthreads();

    for (int kt = 0; kt < CH / 16; kt++) {
        const int buf = kt & 1;
        if (kt + 1 < CH / 16) {           // prefetch next k-tile into registers
            const int k0 = (kt + 1) * 16;
            rA0 = *(const float4*)(X + (size_t)(bm + lr) * CH + k0 + lc);
            rA1 = *(const float4*)(X + (size_t)(bm + lr + 64) * CH + k0 + lc);
            rB0 = *(const float4*)(W + (size_t)(bn + lr) * CH + k0 + lc);
            rB1 = *(const float4*)(W + (size_t)(bn + lr + 64) * CH + k0 + lc);
        }
#pragma unroll
        for (int k = 0; k < 16; k++) {
            float a[8], bb[8];
            *(float4*)(a)      = *(const float4*)&As[buf][k][ty * 8];
            *(float4*)(a + 4)  = *(const float4*)&As[buf][k][ty * 8 + 4];
            *(float4*)(bb)     = *(const float4*)&Bs[buf][k][tx * 8];
            *(float4*)(bb + 4) = *(const float4*)&Bs[buf][k][tx * 8 + 4];
#pragma unroll
            for (int i = 0; i < 8; i++)
#pragma unroll
                for (int j = 0; j < 8; j++)
                    acc[i][j] = fmaf(a[i], bb[j], acc[i][j]);
        }
        if (kt + 1 < CH / 16) {           // stage prefetched tile into other buffer
            const int nb = buf ^ 1;
            As[nb][lc + 0][lr] = rA0.x; As[nb][lc + 1][lr] = rA0.y;
            As[nb][lc + 2][lr] = rA0.z; As[nb][lc + 3][lr] = rA0.w;
            As[nb][lc + 0][lr + 64] = rA1.x; As[nb][lc + 1][lr + 64] = rA1.y;
            As[nb][lc + 2][lr + 64] = rA1.z; As[nb][lc + 3][lr + 64] = rA1.w;
            Bs[nb][lc + 0][lr] = rB0.x; Bs[nb][lc + 1][lr] = rB0.y;
            Bs[nb][lc + 2][lr] = rB0.z; Bs[nb][lc + 3][lr] = rB0.w;
            Bs[nb][lc + 0][lr + 64] = rB1.x; Bs[nb][lc + 1][lr + 64] = rB1.y;
            Bs[nb][lc + 2][lr + 64] = rB1.z; Bs[nb][lc + 3][lr + 64] = rB1.w;
        }
        __syncthreads();
    }

#pragma unroll
    for (int i = 0; i < 8; i++) {
        const int gm = bm + ty * 8 + i;
        const int bi = gm >> 11;          // / SEQ
        const int ni = gm & (SEQ - 1);
#pragma unroll
        for (int jj = 0; jj < 2; jj++) {
            const int gn = bn + tx * 8 + jj * 4;
            const int which = gn / CH;          // 0=Q, 1=K, 2=V (tile never straddles)
            const int rem = gn - which * CH;
            const int hh = rem >> 6;
            const int dd = rem & 63;
            float* dst = (which == 0) ? g_q : ((which == 1) ? g_k : g_v);
            float4 v;
            v.x = acc[i][jj * 4 + 0] + bias[gn + 0];
            v.y = acc[i][jj * 4 + 1] + bias[gn + 1];
            v.z = acc[i][jj * 4 + 2] + bias[gn + 2];
            v.w = acc[i][jj * 4 + 3] + bias[gn + 3];
            *(float4*)(dst + ((((size_t)bi * HEADS + hh) * SEQ + ni) << 6) + dd) = v;
        }
    }
}

// ---------------------------------------------------------------------------
// Kernel 2: flash attention, fp32, online softmax (round-1 proven structure).
// Deltas vs round 1: 1/sqrt(d) folded into the Qs store; P-staging barrier
// relaxed to __syncwarp (all Ps writers a reader needs share its warp).
// ---------------------------------------------------------------------------
#define ATTN_SMEM_FLOATS (64 * 132 + 64 * 68 + 64 * 68 + 64 * 132)
#define ATTN_SMEM_BYTES  (ATTN_SMEM_FLOATS * 4)

__global__ __launch_bounds__(256) void attn_kernel()
{
    extern __shared__ float sm[];
    float* Qs = sm;                       // [d][row]  64 x 132 (128 rows + pad)
    float* Ks = Qs + 64 * 132;            // [d][key]  64 x 68
    float* Vs = Ks + 64 * 68;             // [key][d]  64 x 68
    float* Ps = Vs + 64 * 68;             // [key][row] 64 x 132

    const int n0 = blockIdx.x << 7;       // query tile start
    const int h  = blockIdx.y;
    const int b  = blockIdx.z;
    const int tid = threadIdx.x;
    const int ty = tid >> 4;
    const int tx = tid & 15;

    const float* qbase = g_q + (((size_t)b * HEADS + h) * SEQ + n0) * HDIM;
    const float* kbase = g_k + ((size_t)b * HEADS + h) * SEQ * HDIM;
    const float* vbase = g_v + ((size_t)b * HEADS + h) * SEQ * HDIM;

    // Load Q tile [128][64], store transposed [d][row], pre-scaled by 1/8
#pragma unroll
    for (int it = 0; it < 8; it++) {
        const int lin = (it * 256 + tid) << 2;
        const int row = lin >> 6;
        const int d   = lin & 63;
        float4 v = *(const float4*)(qbase + lin);
        Qs[(d + 0) * 132 + row] = v.x * 0.125f;
        Qs[(d + 1) * 132 + row] = v.y * 0.125f;
        Qs[(d + 2) * 132 + row] = v.z * 0.125f;
        Qs[(d + 3) * 132 + row] = v.w * 0.125f;
    }

    float o[8][4];
    float mrow[8], lrow[8];
#pragma unroll
    for (int i = 0; i < 8; i++) {
        mrow[i] = -1e30f;
        lrow[i] = 0.f;
#pragma unroll
        for (int j = 0; j < 4; j++) o[i][j] = 0.f;
    }

    for (int kt = 0; kt < SEQ / 64; kt++) {
        const float* kb = kbase + (size_t)kt * 64 * HDIM;
        const float* vb = vbase + (size_t)kt * 64 * HDIM;
        __syncthreads();   // prior-iteration readers of Ks/Vs done (also covers Qs fill)
#pragma unroll
        for (int it = 0; it < 4; it++) {
            const int lin = (it * 256 + tid) << 2;
            const int row = lin >> 6;
            const int d   = lin & 63;
            float4 kv = *(const float4*)(kb + lin);
            Ks[(d + 0) * 68 + row] = kv.x;
            Ks[(d + 1) * 68 + row] = kv.y;
            Ks[(d + 2) * 68 + row] = kv.z;
            Ks[(d + 3) * 68 + row] = kv.w;
            float4 vv = *(const float4*)(vb + lin);
            *(float4*)&Vs[row * 68 + d] = vv;
        }
        __syncthreads();

        // S = Q @ K^T  (per-thread 8x4; Q already scaled)
        float s[8][4];
#pragma unroll
        for (int i = 0; i < 8; i++)
#pragma unroll
            for (int j = 0; j < 4; j++) s[i][j] = 0.f;

#pragma unroll 8
        for (int d = 0; d < 64; d++) {
            float a[8];
            *(float4*)(a)     = *(const float4*)&Qs[d * 132 + ty * 8];
            *(float4*)(a + 4) = *(const float4*)&Qs[d * 132 + ty * 8 + 4];
            float4 kk = *(const float4*)&Ks[d * 68 + tx * 4];
#pragma unroll
            for (int i = 0; i < 8; i++) {
                s[i][0] = fmaf(a[i], kk.x, s[i][0]);
                s[i][1] = fmaf(a[i], kk.y, s[i][1]);
                s[i][2] = fmaf(a[i], kk.z, s[i][2]);
                s[i][3] = fmaf(a[i], kk.w, s[i][3]);
            }
        }

        // Online softmax update (row groups = 16 lanes sharing ty)
#pragma unroll
        for (int i = 0; i < 8; i++) {
            float mx = fmaxf(fmaxf(s[i][0], s[i][1]), fmaxf(s[i][2], s[i][3]));
#pragma unroll
            for (int off = 1; off < 16; off <<= 1)
                mx = fmaxf(mx, __shfl_xor_sync(0xffffffffu, mx, off, 16));
            const float mnew = fmaxf(mrow[i], mx);
            const float alpha = __expf(mrow[i] - mnew);
            mrow[i] = mnew;
            float rs = 0.f;
#pragma unroll
            for (int j = 0; j < 4; j++) {
                const float p = __expf(s[i][j] - mnew);
                s[i][j] = p;
                rs += p;
            }
#pragma unroll
            for (int off = 1; off < 16; off <<= 1)
                rs += __shfl_xor_sync(0xffffffffu, rs, off, 16);
            lrow[i] = lrow[i] * alpha + rs;
#pragma unroll
            for (int j = 0; j < 4; j++) o[i][j] *= alpha;
            // stage P transposed: [key][row]
#pragma unroll
            for (int j = 0; j < 4; j++)
                Ps[(tx * 4 + j) * 132 + ty * 8 + i] = s[i][j];
        }
        __syncwarp();   // Ps writers needed by this thread are all in its warp

        // O += P @ V  (per-thread rows ty*8.., dims tx*4..)
#pragma unroll 8
        for (int j = 0; j < 64; j++) {
            float p[8];
            *(float4*)(p)     = *(const float4*)&Ps[j * 132 + ty * 8];
            *(float4*)(p + 4) = *(const float4*)&Ps[j * 132 + ty * 8 + 4];
            float4 vv = *(const float4*)&Vs[j * 68 + tx * 4];
#pragma unroll
            for (int i = 0; i < 8; i++) {
                o[i][0] = fmaf(p[i], vv.x, o[i][0]);
                o[i][1] = fmaf(p[i], vv.y, o[i][1]);
                o[i][2] = fmaf(p[i], vv.z, o[i][2]);
                o[i][3] = fmaf(p[i], vv.w, o[i][3]);
            }
        }
    }

    // Normalize and write [B,N,C]
    float* ob = g_att + ((size_t)b * SEQ + n0) * CH + h * HDIM;
#pragma unroll
    for (int i = 0; i < 8; i++) {
        const float inv = 1.0f / lrow[i];
        float4 v;
        v.x = o[i][0] * inv; v.y = o[i][1] * inv;
        v.z = o[i][2] * inv; v.w = o[i][3] * inv;
        *(float4*)(ob + (size_t)(ty * 8 + i) * CH + tx * 4) = v;
    }
}

// ---------------------------------------------------------------------------
// Kernel 3: output projection. out = g_att @ proj_w^T + proj_b.
// Same double-buffered structure as kernel 1.
// ---------------------------------------------------------------------------
__global__ __launch_bounds__(256, 2) void proj_gemm_kernel(
    const float* __restrict__ W, const float* __restrict__ bias,
    float* __restrict__ out)
{
    __shared__ float As[2][16][132];
    __shared__ float Bs[2][16][132];
    const int bm = blockIdx.y << 7;
    const int bn = blockIdx.x << 7;
    const int tid = threadIdx.x;
    const int ty = tid >> 4;
    const int tx = tid & 15;
    const int lr = tid >> 2;
    const int lc = (tid & 3) << 2;

    float acc[8][8];
#pragma unroll
    for (int i = 0; i < 8; i++)
#pragma unroll
        for (int j = 0; j < 8; j++) acc[i][j] = 0.f;

    float4 rA0 = *(const float4*)(g_att + (size_t)(bm + lr) * CH + lc);
    float4 rA1 = *(const float4*)(g_att + (size_t)(bm + lr + 64) * CH + lc);
    float4 rB0 = *(const float4*)(W + (size_t)(bn + lr) * CH + lc);
    float4 rB1 = *(const float4*)(W + (size_t)(bn + lr + 64) * CH + lc);
    As[0][lc + 0][lr] = rA0.x; As[0][lc + 1][lr] = rA0.y;
    As[0][lc + 2][lr] = rA0.z; As[0][lc + 3][lr] = rA0.w;
    As[0][lc + 0][lr + 64] = rA1.x; As[0][lc + 1][lr + 64] = rA1.y;
    As[0][lc + 2][lr + 64] = rA1.z; As[0][lc + 3][lr + 64] = rA1.w;
    Bs[0][lc + 0][lr] = rB0.x; Bs[0][lc + 1][lr] = rB0.y;
    Bs[0][lc + 2][lr] = rB0.z; Bs[0][lc + 3][lr] = rB0.w;
    Bs[0][lc + 0][lr + 64] = rB1.x; Bs[0][lc + 1][lr + 64] = rB1.y;
    Bs[0][lc + 2][lr + 64] = rB1.z; Bs[0][lc + 3][lr + 64] = rB1.w;
    __syncthreads();

    for (int kt = 0; kt < CH / 16; kt++) {
        const int buf = kt & 1;
        if (kt + 1 < CH / 16) {
            const int k0 = (kt + 1) * 16;
            rA0 = *(const float4*)(g_att + (size_t)(bm + lr) * CH + k0 + lc);
            rA1 = *(const float4*)(g_att + (size_t)(bm + lr + 64) * CH + k0 + lc);
            rB0 = *(const float4*)(W + (size_t)(bn + lr) * CH + k0 + lc);
            rB1 = *(const float4*)(W + (size_t)(bn + lr + 64) * CH + k0 + lc);
        }
#pragma unroll
        for (int k = 0; k < 16; k++) {
            float a[8], bb[8];
            *(float4*)(a)      = *(const float4*)&As[buf][k][ty * 8];
            *(float4*)(a + 4)  = *(const float4*)&As[buf][k][ty * 8 + 4];
            *(float4*)(bb)     = *(const float4*)&Bs[buf][k][tx * 8];
            *(float4*)(bb + 4) = *(const float4*)&Bs[buf][k][tx * 8 + 4];
#pragma unroll
            for (int i = 0; i < 8; i++)
#pragma unroll
                for (int j = 0; j < 8; j++)
                    acc[i][j] = fmaf(a[i], bb[j], acc[i][j]);
        }
        if (kt + 1 < CH / 16) {
            const int nb = buf ^ 1;
            As[nb][lc + 0][lr] = rA0.x; As[nb][lc + 1][lr] = rA0.y;
            As[nb][lc + 2][lr] = rA0.z; As[nb][lc + 3][lr] = rA0.w;
            As[nb][lc + 0][lr + 64] = rA1.x; As[nb][lc + 1][lr + 64] = rA1.y;
            As[nb][lc + 2][lr + 64] = rA1.z; As[nb][lc + 3][lr + 64] = rA1.w;
            Bs[nb][lc + 0][lr] = rB0.x; Bs[nb][lc + 1][lr] = rB0.y;
            Bs[nb][lc + 2][lr] = rB0.z; Bs[nb][lc + 3][lr] = rB0.w;
            Bs[nb][lc + 0][lr + 64] = rB1.x; Bs[nb][lc + 1][lr + 64] = rB1.y;
            Bs[nb][lc + 2][lr + 64] = rB1.z; Bs[nb][lc + 3][lr + 64] = rB1.w;
        }
        __syncthreads();
    }

#pragma unroll
    for (int i = 0; i < 8; i++) {
        const int gm = bm + ty * 8 + i;
#pragma unroll
        for (int jj = 0; jj < 2; jj++) {
            const int gn = bn + tx * 8 + jj * 4;
            float4 v;
            v.x = acc[i][jj * 4 + 0] + bias[gn + 0];
            v.y = acc[i][jj * 4 + 1] + bias[gn + 1];
            v.z = acc[i][jj * 4 + 2] + bias[gn + 2];
            v.w = acc[i][jj * 4 + 3] + bias[gn + 3];
            *(float4*)(out + (size_t)gm * CH + gn) = v;
        }
    }
}

// ---------------------------------------------------------------------------
extern "C" void kernel_launch(void* const* d_in, const int* in_sizes, int n_in,
                              void* d_out, int out_size)
{
    const float* x      = (const float*)d_in[0];
    const float* qkv_w  = (const float*)d_in[1];
    const float* qkv_b  = (const float*)d_in[2];
    const float* proj_w = (const float*)d_in[3];
    const float* proj_b = (const float*)d_in[4];
    float* out = (float*)d_out;

    (void)in_sizes; (void)n_in; (void)out_size;

    // QKV projection: M=8192, N=2304, K=768
    qkv_gemm_kernel<<<dim3(2304 / 128, (BATCH * SEQ) / 128), 256>>>(x, qkv_w, qkv_b);

    // Flash attention
    cudaFuncSetAttribute(attn_kernel, cudaFuncAttributeMaxDynamicSharedMemorySize,
                         ATTN_SMEM_BYTES);
    attn_kernel<<<dim3(SEQ / 128, HEADS, BATCH), 256, ATTN_SMEM_BYTES>>>();

    // Output projection: M=8192, N=768, K=768
    proj_gemm_kernel<<<dim3(CH / 128, (BATCH * SEQ) / 128), 256>>>(proj_w, proj_b, out);
}